// round 15
// baseline (speedup 1.0000x reference)
#include <cuda_runtime.h>
#include <cstdint>

// Problem constants (fixed by the reference)
#define SEQ   1024
#define BSZ   16
#define DIM   1024
#define SIDE  32
#define BD    (BSZ * DIM)

#define DPB   32               // channels per block = warps per block
#define IPB   2                // images per block / per warp
#define RCH   4                // rows per chunk
#define NCH   (SIDE / RCH)     // 8 chunks
#define SCs   33               // smem col stride (floats), == 1 mod 32
#define SIs   1057             // smem image stride = 32*33+1, == 1 mod 32
#define SLOT  (IPB * SIs)      // 2114 floats per (buffer,row) slot
#define SMEM_FLOATS (2 * RCH * SLOT)
#define SMEM_BYTES  (SMEM_FLOATS * 4)   // 67648 B -> 2 blocks/SM

// 4-byte async copy gmem->smem (scatter-transpose with zero register cost)
__device__ __forceinline__ void cpa4(uint32_t dst, const float* src) {
    asm volatile("cp.async.ca.shared.global [%0], [%1], 4;" :: "r"(dst), "l"(src));
}

// out[s,b,d] = silu( conv2d_causal(x, K_d)[s] + x[s,b,d]*omega[d] )
// via running the 2-state 2D SSM recurrence directly on x.
// Block: 32 channels x 2 images, 1024 threads, 2 blocks/SM, grid 256.
// Compute: warp = channel; lane (ib=lane>>4, g=lane&15) owns cols 2g..2g+1 of
// image ib. Per row-component: 2-FMA serial prefix + 4-step scan over 16
// groups; left-boundary v via local duplication; hin = (S - Y1)/a1^2 (no shfl).
// IO: warp = column, lane = channel -> one 128B line per warp op; cp.async
// scatters into padded smem (no prefetch registers).
__global__ __launch_bounds__(1024, 2) void ssm2d_kernel(
    const float* __restrict__ x,
    const float* __restrict__ A1, const float* __restrict__ A2,
    const float* __restrict__ B1, const float* __restrict__ B2,
    const float* __restrict__ C1, const float* __restrict__ C2,
    const float* __restrict__ omega,
    float* __restrict__ out)
{
    extern __shared__ float buf[];
    const uint32_t sb = (uint32_t)__cvta_generic_to_shared(buf);

    const int tid  = threadIdx.x;
    const int w    = tid >> 5;        // warp id: compute channel / io column
    const int lane = tid & 31;
    const int ib   = lane >> 4;       // image (compute role), 0..1
    const int g    = lane & 15;       // column group (cols 2g, 2g+1)

    const int d0 = blockIdx.x * DPB;
    const int b0 = blockIdx.y * IPB;
    const int d  = d0 + w;

    // io role: gmem off = s*BD + (b0+im)*DIM + d0 + lane, s = row*32 + w
    const int gio = w * BD + b0 * DIM + d0 + lane;
    // io smem idx = slot*SLOT + im*SIs + w*SCs + lane   (col=w, ch=lane)
    const int sio = w * SCs + lane;

    const float SC = 0.70710678118654752440f;  // sqrt(1/2)

    float a1[2], a2[2], b1[2], b2[2], c1[2], c2[2];
#pragma unroll
    for (int k = 0; k < 2; ++k) {
        a1[k] = 0.5f / (1.f + __expf(-A1[d * 2 + k]));
        a2[k] = 0.5f / (1.f + __expf(-A2[d * 2 + k]));
        b1[k] = 0.5f / (1.f + __expf(-B1[d * 2 + k]));
        b2[k] = 0.5f / (1.f + __expf(-B2[d * 2 + k]));
        c1[k] = C1[d * 2 + k] * SC;
        c2[k] = C2[d * 2 + k] * SC;
    }
    const float om = omega[d];

    // live: p2 = a1^2 (group coefficient) and its inverse; higher powers remat
    float p2[2], ip2[2];
#pragma unroll
    for (int k = 0; k < 2; ++k) {
        p2[k]  = a1[k] * a1[k];
        ip2[k] = __fdividef(1.f, p2[k]);
    }

    // previous-row state: own 2 columns + duplicated left column (2g-1)
    float h[2][2] = {{0.f,0.f},{0.f,0.f}};
    float v[2][2] = {{0.f,0.f},{0.f,0.f}};
    float vst[2] = {0.f, 0.f};   // v at column 2g-1
    float hst[2] = {0.f, 0.f};   // h at column 2g-1 of previous row

    const int cbase = ib * SIs + w;   // compute smem base (+ slot, + col*SCs)

    // ---- prologue: async-load chunk 0 into buffer 0 ----
#pragma unroll
    for (int t = 0; t < RCH * IPB; ++t) {
        const int r = t >> 1, im = t & 1;
        cpa4(sb + 4u * (r * SLOT + im * SIs + sio),
             x + gio + r * (SIDE * BD) + im * DIM);
    }
    asm volatile("cp.async.commit_group;" ::: "memory");

    for (int c = 0; c < NCH; ++c) {
        const int p = c & 1;
        asm volatile("cp.async.wait_group 0;" ::: "memory");  // chunk c arrived
        __syncthreads();   // all async writes + silu(c-1) visible block-wide

        // (1) write back chunk c-1 from buf[p^1] (gather scalar -> 128B STG)
        if (c > 0) {
            const int gwb = gio + (c - 1) * (RCH * SIDE * BD);
#pragma unroll
            for (int t = 0; t < RCH * IPB; ++t) {
                const int r = t >> 1, im = t & 1;
                const float val = buf[((p ^ 1) * RCH + r) * SLOT + im * SIs + sio];
                out[gwb + r * (SIDE * BD) + im * DIM] = val;
            }
        }

        // (2) async-load chunk c+1 into buf[p^1] (same slots this thread just
        //     read in (1); same-thread program order makes the WAR safe)
        if (c + 1 < NCH) {
            const int gld = gio + (c + 1) * (RCH * SIDE * BD);
#pragma unroll
            for (int t = 0; t < RCH * IPB; ++t) {
                const int r = t >> 1, im = t & 1;
                cpa4(sb + 4u * (((p ^ 1) * RCH + r) * SLOT + im * SIs + sio),
                     x + gld + r * (SIDE * BD) + im * DIM);
            }
            asm volatile("cp.async.commit_group;" ::: "memory");
        }

        // (3) recurrence on chunk c (reads/writes buf[p] only)
#pragma unroll
        for (int r = 0; r < RCH; ++r) {
            const int base = (p * RCH + r) * SLOT + cbase;
            const float x0 = buf[base + (2 * g + 0) * SCs];
            const float x1 = buf[base + (2 * g + 1) * SCs];
            // x of column 2g-1 (left neighbor's last column); 0 for g==0
            const float xm1 = (g > 0) ? buf[base + (2 * g - 1) * SCs] : 0.f;

            float o0 = om * x0, o1 = om * x1;

#pragma unroll
            for (int k = 0; k < 2; ++k) {
                // duplicated left-column vertical update (local, no shfl);
                // for g==0: hst=vst=xm1=0 -> stays 0
                vst[k] = fmaf(a2[k], hst[k], fmaf(a1[k], vst[k], b2[k] * xm1));

                // vertical update for the 2 owned columns
                float v0 = fmaf(a2[k], h[k][0], fmaf(a1[k], v[k][0], b2[k] * x0));
                float v1 = fmaf(a2[k], h[k][1], fmaf(a1[k], v[k][1], b2[k] * x1));

                // local serial prefix of h-drive, seeded by local vst
                float Y0 = fmaf(a2[k], vst[k], b1[k] * x0);
                float Y1 = fmaf(a1[k], Y0, fmaf(a2[k], v0, b1[k] * x1));

                // rematerialized scan coefficients
                const float p4  = p2[k] * p2[k];
                const float p8  = p4 * p4;
                const float p16 = p8 * p8;

                // 4-step scan over the 16 groups of this image half,
                // group coefficient a1^2 (guard prevents cross-image mixing)
                float S = Y1, t;
                t = __shfl_up_sync(0xffffffffu, S, 1);
                if (g >= 1) S = fmaf(p2[k], t, S);
                t = __shfl_up_sync(0xffffffffu, S, 2);
                if (g >= 2) S = fmaf(p4, t, S);
                t = __shfl_up_sync(0xffffffffu, S, 4);
                if (g >= 4) S = fmaf(p8, t, S);
                t = __shfl_up_sync(0xffffffffu, S, 8);
                if (g >= 8) S = fmaf(p16, t, S);

                // hin = h at column 2g-1, recovered without a shfl:
                // S = p2*S_prev + Y1  =>  S_prev = (S - Y1)/p2 (exact 0 @ g==0)
                const float hin = (S - Y1) * ip2[k];
                hst[k] = hin;   // left-column h for next row's vst update

                // reconstruct h for the 2 owned columns
                float h0 = fmaf(a1[k], hin, Y0);
                float h1 = fmaf(p2[k], hin, Y1);

                h[k][0] = h0; h[k][1] = h1;
                v[k][0] = v0; v[k][1] = v1;

                o0 = fmaf(c1[k], h0, fmaf(c2[k], v0, o0));
                o1 = fmaf(c1[k], h1, fmaf(c2[k], v1, o1));
            }

            // silu + stage output in place (same slots this thread read)
            buf[base + (2 * g + 0) * SCs] = o0 * __fdividef(1.f, 1.f + __expf(-o0));
            buf[base + (2 * g + 1) * SCs] = o1 * __fdividef(1.f, 1.f + __expf(-o1));
        }
    }

    // ---- epilogue: write back final chunk ----
    __syncthreads();
    {
        const int q = (NCH - 1) & 1;
        const int gwb = gio + (NCH - 1) * (RCH * SIDE * BD);
#pragma unroll
        for (int t = 0; t < RCH * IPB; ++t) {
            const int r = t >> 1, im = t & 1;
            const float val = buf[(q * RCH + r) * SLOT + im * SIs + sio];
            out[gwb + r * (SIDE * BD) + im * DIM] = val;
        }
    }
}

extern "C" void kernel_launch(void* const* d_in, const int* in_sizes, int n_in,
                              void* d_out, int out_size)
{
    const float* x     = (const float*)d_in[0];
    const float* A1    = (const float*)d_in[1];
    const float* A2    = (const float*)d_in[2];
    const float* B1    = (const float*)d_in[3];
    const float* B2    = (const float*)d_in[4];
    const float* C1    = (const float*)d_in[5];
    const float* C2    = (const float*)d_in[6];
    const float* omega = (const float*)d_in[7];
    float* out = (float*)d_out;

    cudaFuncSetAttribute(ssm2d_kernel,
                         cudaFuncAttributeMaxDynamicSharedMemorySize, SMEM_BYTES);

    dim3 block(1024);
    dim3 grid(DIM / DPB, BSZ / IPB);   // 32 x 8 = 256 blocks
    ssm2d_kernel<<<grid, block, SMEM_BYTES>>>(x, A1, A2, B1, B2, C1, C2, omega, out);
}

// round 16
// speedup vs baseline: 1.7307x; 1.7307x over previous
#include <cuda_runtime.h>
#include <cstdint>

// Problem constants (fixed by the reference)
#define SEQ   1024
#define BSZ   16
#define DIM   1024
#define SIDE  32
#define BD    (BSZ * DIM)

#define DPB   32               // channels per block = warps per block
#define IPB   4                // images per block
#define RCH   4                // rows per chunk
#define NCH   (SIDE / RCH)     // 8 chunks
#define NBUF  3                // triple buffering (depth-2 prefetch)
#define SCs   33               // smem col stride (floats), == 1 mod 32
#define SIs   1057             // smem image stride = 32*33+1, == 1 mod 32
#define SLOT  (IPB * SIs)      // 4228 floats per (buffer,row) slot
#define SMEM_FLOATS (NBUF * RCH * SLOT)
#define SMEM_BYTES  (SMEM_FLOATS * 4)   // 202944 B (fits 227KB cap)

// 4-byte async copy gmem->smem (scatter-transpose with zero register cost)
__device__ __forceinline__ void cpa4(uint32_t dst, const float* src) {
    asm volatile("cp.async.ca.shared.global [%0], [%1], 4;" :: "r"(dst), "l"(src));
}

// out[s,b,d] = silu( conv2d_causal(x, K_d)[s] + x[s,b,d]*omega[d] )
// via running the 2-state 2D SSM recurrence directly on x.
// Block: 32 channels x 4 images. Compute: warp = channel, lane (ib=lane>>3,
// g=lane&7) owns cols 4g..4g+3 of image ib. 3 shfls per row-component:
//  - left-boundary v via local duplication of column 4g-1's vertical state,
//  - hin recovered from the inclusive scan: hin = (S - Y3)/p4 (no shfl).
// IO: warp = column, lane = channel -> one 128B line per warp op.
// Triple-buffered cp.async pipeline: chunk c+2 is issued while chunk c is
// computed; wait_group 1 makes the per-chunk wait a no-op (except the last).
__global__ __launch_bounds__(1024, 1) void ssm2d_kernel(
    const float* __restrict__ x,
    const float* __restrict__ A1, const float* __restrict__ A2,
    const float* __restrict__ B1, const float* __restrict__ B2,
    const float* __restrict__ C1, const float* __restrict__ C2,
    const float* __restrict__ omega,
    float* __restrict__ out)
{
    extern __shared__ float buf[];
    const uint32_t sb = (uint32_t)__cvta_generic_to_shared(buf);

    const int tid  = threadIdx.x;
    const int w    = tid >> 5;        // warp id: compute channel / io column
    const int lane = tid & 31;
    const int ib   = lane >> 3;       // image (compute role)
    const int g    = lane & 7;        // column group (compute role)

    const int d0 = blockIdx.x * DPB;
    const int b0 = blockIdx.y * IPB;
    const int d  = d0 + w;

    // io role: gmem off = s*BD + (b0+im)*DIM + d0 + lane, s = row*32 + w
    const int gio = w * BD + b0 * DIM + d0 + lane;
    // io smem idx = slot*SLOT + im*SIs + w*SCs + lane
    const int sio = w * SCs + lane;

    const float SC = 0.70710678118654752440f;  // sqrt(1/2)

    float a1[2], a2[2], b1[2], b2[2], c1[2], c2[2];
#pragma unroll
    for (int k = 0; k < 2; ++k) {
        a1[k] = 0.5f / (1.f + __expf(-A1[d * 2 + k]));
        a2[k] = 0.5f / (1.f + __expf(-A2[d * 2 + k]));
        b1[k] = 0.5f / (1.f + __expf(-B1[d * 2 + k]));
        b2[k] = 0.5f / (1.f + __expf(-B2[d * 2 + k]));
        c1[k] = C1[d * 2 + k] * SC;
        c2[k] = C2[d * 2 + k] * SC;
    }
    const float om = omega[d];

    // live coefficient powers: p2, p4, 1/p4 ; p3/p8/p16 rematerialized per row
    float p2[2], p4[2], ip4[2];
#pragma unroll
    for (int k = 0; k < 2; ++k) {
        p2[k]  = a1[k] * a1[k];
        p4[k]  = p2[k] * p2[k];
        ip4[k] = __fdividef(1.f, p4[k]);
    }

    // previous-row state: own 4 columns + duplicated left column (4g-1)
    float h[2][4] = {{0.f,0.f,0.f,0.f},{0.f,0.f,0.f,0.f}};
    float v[2][4] = {{0.f,0.f,0.f,0.f},{0.f,0.f,0.f,0.f}};
    float vst[2] = {0.f, 0.f};   // v at column 4g-1 (previous row -> updated)
    float hst[2] = {0.f, 0.f};   // h at column 4g-1 of previous row

    const int cbase = ib * SIs + w;   // compute smem base (+ slot, + col*SCs)

    // ---- prologue: async-load chunks 0 and 1 as two groups ----
#pragma unroll
    for (int t = 0; t < RCH * IPB; ++t) {
        const int r = t >> 2, im = t & 3;
        cpa4(sb + 4u * ((0 * RCH + r) * SLOT + im * SIs + sio),
             x + gio + r * (SIDE * BD) + im * DIM);
    }
    asm volatile("cp.async.commit_group;" ::: "memory");
#pragma unroll
    for (int t = 0; t < RCH * IPB; ++t) {
        const int r = t >> 2, im = t & 3;
        cpa4(sb + 4u * ((1 * RCH + r) * SLOT + im * SIs + sio),
             x + gio + (RCH + r) * (SIDE * BD) + im * DIM);
    }
    asm volatile("cp.async.commit_group;" ::: "memory");

    int bi = 0;   // buffer index of chunk c (c mod 3)
    for (int c = 0; c < NCH; ++c) {
        const int bo = (bi + 2 >= NBUF) ? bi + 2 - NBUF : bi + 2;  // (c-1)%3 == (c+2)%3

        // chunk c's group is 2 commits back -> usually already complete
        if (c < NCH - 1) {
            asm volatile("cp.async.wait_group 1;" ::: "memory");
        } else {
            asm volatile("cp.async.wait_group 0;" ::: "memory");
        }
        __syncthreads();   // async writes for chunk c + silu(c-1) visible

        // (1) write back chunk c-1 from buf[bo] (gather scalar -> 128B STG)
        if (c > 0) {
            const int gwb = gio + (c - 1) * (RCH * SIDE * BD);
#pragma unroll
            for (int t = 0; t < RCH * IPB; ++t) {
                const int r = t >> 2, im = t & 3;
                const float val = buf[(bo * RCH + r) * SLOT + im * SIs + sio];
                out[gwb + r * (SIDE * BD) + im * DIM] = val;
            }
        }

        // (2) async-load chunk c+2 into buf[bo] (same slots this thread just
        //     read in (1); LDS data already consumed -> WAR safe in-thread)
        if (c + 2 < NCH) {
            const int gld = gio + (c + 2) * (RCH * SIDE * BD);
#pragma unroll
            for (int t = 0; t < RCH * IPB; ++t) {
                const int r = t >> 2, im = t & 3;
                cpa4(sb + 4u * ((bo * RCH + r) * SLOT + im * SIs + sio),
                     x + gld + r * (SIDE * BD) + im * DIM);
            }
            asm volatile("cp.async.commit_group;" ::: "memory");
        }

        // (3) recurrence on chunk c (reads/writes buf[bi] only)
#pragma unroll
        for (int r = 0; r < RCH; ++r) {
            const int base = (bi * RCH + r) * SLOT + cbase;
            float xs[4];
#pragma unroll
            for (int cc = 0; cc < 4; ++cc) xs[cc] = buf[base + (4 * g + cc) * SCs];
            // x of column 4g-1 (left neighbor's last column); 0 for g==0
            const float xm1 = (g > 0) ? buf[base + (4 * g - 1) * SCs] : 0.f;

            float o0 = om * xs[0], o1 = om * xs[1];
            float o2 = om * xs[2], o3 = om * xs[3];

#pragma unroll
            for (int k = 0; k < 2; ++k) {
                // duplicated left-column vertical update (local, no shfl);
                // for g==0: hst=vst=xm1=0 -> stays 0
                vst[k] = fmaf(a2[k], hst[k], fmaf(a1[k], vst[k], b2[k] * xm1));

                // vertical update for the 4 owned columns
                float v0 = fmaf(a2[k], h[k][0], fmaf(a1[k], v[k][0], b2[k] * xs[0]));
                float v1 = fmaf(a2[k], h[k][1], fmaf(a1[k], v[k][1], b2[k] * xs[1]));
                float v2 = fmaf(a2[k], h[k][2], fmaf(a1[k], v[k][2], b2[k] * xs[2]));
                float v3 = fmaf(a2[k], h[k][3], fmaf(a1[k], v[k][3], b2[k] * xs[3]));

                // local serial prefix of h-drive, seeded by local vst
                float Y0 = fmaf(a2[k], vst[k], b1[k] * xs[0]);
                float Y1 = fmaf(a1[k], Y0, fmaf(a2[k], v0, b1[k] * xs[1]));
                float Y2 = fmaf(a1[k], Y1, fmaf(a2[k], v1, b1[k] * xs[2]));
                float Y3 = fmaf(a1[k], Y2, fmaf(a2[k], v2, b1[k] * xs[3]));

                // rematerialized coefficient powers
                const float p8  = p4[k] * p4[k];
                const float p16 = p8 * p8;
                const float p3  = p2[k] * a1[k];

                // 3-step scan over 8-lane group, coefficient a1^4
                float S = Y3, t;
                t = __shfl_up_sync(0xffffffffu, S, 1);
                if (g >= 1) S = fmaf(p4[k], t, S);
                t = __shfl_up_sync(0xffffffffu, S, 2);
                if (g >= 2) S = fmaf(p8, t, S);
                t = __shfl_up_sync(0xffffffffu, S, 4);
                if (g >= 4) S = fmaf(p16, t, S);

                // hin = h at column 4g-1, recovered without a shfl:
                // S = p4*S_prev + Y3  =>  S_prev = (S - Y3)/p4 (exact 0 @ g==0)
                const float hin = (S - Y3) * ip4[k];
                hst[k] = hin;   // left-column h for next row's vst update

                // reconstruct h for the 4 owned columns
                float h0 = fmaf(a1[k], hin, Y0);
                float h1 = fmaf(p2[k], hin, Y1);
                float h2 = fmaf(p3,    hin, Y2);
                float h3 = fmaf(p4[k], hin, Y3);

                h[k][0] = h0; h[k][1] = h1; h[k][2] = h2; h[k][3] = h3;
                v[k][0] = v0; v[k][1] = v1; v[k][2] = v2; v[k][3] = v3;

                o0 = fmaf(c1[k], h0, fmaf(c2[k], v0, o0));
                o1 = fmaf(c1[k], h1, fmaf(c2[k], v1, o1));
                o2 = fmaf(c1[k], h2, fmaf(c2[k], v2, o2));
                o3 = fmaf(c1[k], h3, fmaf(c2[k], v3, o3));
            }

            // silu + stage output in place (same slots this thread read)
            buf[base + (4 * g + 0) * SCs] = o0 * __fdividef(1.f, 1.f + __expf(-o0));
            buf[base + (4 * g + 1) * SCs] = o1 * __fdividef(1.f, 1.f + __expf(-o1));
            buf[base + (4 * g + 2) * SCs] = o2 * __fdividef(1.f, 1.f + __expf(-o2));
            buf[base + (4 * g + 3) * SCs] = o3 * __fdividef(1.f, 1.f + __expf(-o3));
        }

        bi = (bi + 1 >= NBUF) ? 0 : bi + 1;
    }

    // ---- epilogue: write back final chunk (buffer (NCH-1)%NBUF) ----
    __syncthreads();
    {
        const int q = (NCH - 1) % NBUF;
        const int gwb = gio + (NCH - 1) * (RCH * SIDE * BD);
#pragma unroll
        for (int t = 0; t < RCH * IPB; ++t) {
            const int r = t >> 2, im = t & 3;
            const float val = buf[(q * RCH + r) * SLOT + im * SIs + sio];
            out[gwb + r * (SIDE * BD) + im * DIM] = val;
        }
    }
}

extern "C" void kernel_launch(void* const* d_in, const int* in_sizes, int n_in,
                              void* d_out, int out_size)
{
    const float* x     = (const float*)d_in[0];
    const float* A1    = (const float*)d_in[1];
    const float* A2    = (const float*)d_in[2];
    const float* B1    = (const float*)d_in[3];
    const float* B2    = (const float*)d_in[4];
    const float* C1    = (const float*)d_in[5];
    const float* C2    = (const float*)d_in[6];
    const float* omega = (const float*)d_in[7];
    float* out = (float*)d_out;

    cudaFuncSetAttribute(ssm2d_kernel,
                         cudaFuncAttributeMaxDynamicSharedMemorySize, SMEM_BYTES);

    dim3 block(1024);
    dim3 grid(DIM / DPB, BSZ / IPB);   // 32 x 4 = 128 blocks
    ssm2d_kernel<<<grid, block, SMEM_BYTES>>>(x, A1, A2, B1, B2, C1, C2, omega, out);
}

// round 17
// speedup vs baseline: 1.9175x; 1.1079x over previous
#include <cuda_runtime.h>
#include <cstdint>

// Problem constants (fixed by the reference)
#define SEQ   1024
#define BSZ   16
#define DIM   1024
#define SIDE  32
#define BD    (BSZ * DIM)

#define DPB   8                // channels per block = warps per block
#define IPB   4                // images per block
#define RCH   4                // rows per chunk
#define NCH   (SIDE / RCH)     // 8 chunks
#define CHS   36               // smem channel stride (words); col stride = 1
#define IMS   (DPB * CHS + 1)  // 289 image stride, == 1 mod 32
#define SLOT  (IPB * IMS)      // 1156 words per (buffer,row) slot
#define SMEM_FLOATS (2 * RCH * SLOT)
#define SMEM_BYTES  (SMEM_FLOATS * 4)   // 36992 B -> 4 blocks/SM (RF-exact)

// 4-byte async copy gmem->smem (scatter-transpose with zero register cost)
__device__ __forceinline__ void cpa4(uint32_t dst, const float* src) {
    asm volatile("cp.async.ca.shared.global [%0], [%1], 4;" :: "r"(dst), "l"(src));
}

// silu(y) = y*sigmoid(y) = m + m*tanh(m), m = y/2  (1 MUFU instead of 2)
__device__ __forceinline__ float silu_f(float y) {
    float m = 0.5f * y, t;
    asm("tanh.approx.f32 %0, %1;" : "=f"(t) : "f"(m));
    return fmaf(m, t, m);
}

// out[s,b,d] = silu( conv2d_causal(x, K_d)[s] + x[s,b,d]*omega[d] )
// via running the 2-state 2D SSM recurrence directly on x.
// Block: 8 channels x 4 images, 256 threads, 4 independent blocks/SM ->
// 4 interleaved barrier groups hide each other's sync/load bubbles.
// Compute: warp = channel; lane (ib=lane>>3, g=lane&7) owns cols 4g..4g+3
// (stride-1 in smem) of image ib. IO: ch = tid&7 (32B sector-exact gmem),
// col = (tid>>3)&31; smem banks conflict-free for all three roles.
__global__ __launch_bounds__(256, 4) void ssm2d_kernel(
    const float* __restrict__ x,
    const float* __restrict__ A1, const float* __restrict__ A2,
    const float* __restrict__ B1, const float* __restrict__ B2,
    const float* __restrict__ C1, const float* __restrict__ C2,
    const float* __restrict__ omega,
    float* __restrict__ out)
{
    extern __shared__ float buf[];
    const uint32_t sb = (uint32_t)__cvta_generic_to_shared(buf);

    const int tid  = threadIdx.x;
    const int w    = tid >> 5;        // warp id == channel within block
    const int lane = tid & 31;
    const int ib   = lane >> 3;       // image (compute role)
    const int g    = lane & 7;        // column group (cols 4g..4g+3)

    const int d0 = blockIdx.x * DPB;
    const int b0 = blockIdx.y * IPB;
    const int d  = d0 + w;

    // io role: ch = tid&7, col = (tid>>3)&31, images looped
    const int ioh = tid & 7;
    const int ioc = (tid >> 3) & 31;
    // gmem: s*BD + (b0+im)*DIM + d0 + ioh, s = (chunk*RCH + r)*SIDE + ioc
    const int gio = ioc * BD + b0 * DIM + d0 + ioh;
    // smem: slot*SLOT + im*IMS + ioh*CHS + ioc
    const int sio = ioh * CHS + ioc;

    const float SC = 0.70710678118654752440f;  // sqrt(1/2)

    float a1[2], a2[2], b1[2], b2[2], c1[2], c2[2];
#pragma unroll
    for (int k = 0; k < 2; ++k) {
        a1[k] = 0.5f / (1.f + __expf(-A1[d * 2 + k]));
        a2[k] = 0.5f / (1.f + __expf(-A2[d * 2 + k]));
        b1[k] = 0.5f / (1.f + __expf(-B1[d * 2 + k]));
        b2[k] = 0.5f / (1.f + __expf(-B2[d * 2 + k]));
        c1[k] = C1[d * 2 + k] * SC;
        c2[k] = C2[d * 2 + k] * SC;
    }
    const float om = omega[d];

    // keep only p2, p4 live; p3/p8/p16 rematerialized per row (64-reg budget)
    float p2[2], p4[2];
#pragma unroll
    for (int k = 0; k < 2; ++k) { p2[k] = a1[k] * a1[k]; p4[k] = p2[k] * p2[k]; }

    // previous-row state for this lane's 4 columns, both components
    float h[2][4] = {{0.f,0.f,0.f,0.f},{0.f,0.f,0.f,0.f}};
    float v[2][4] = {{0.f,0.f,0.f,0.f},{0.f,0.f,0.f,0.f}};

    const int cbase = ib * IMS + w * CHS;   // compute smem base (+ slot, + 4g+cc)

    // ---- prologue: async-load chunk 0 into buffer 0 ----
#pragma unroll
    for (int t = 0; t < RCH * IPB; ++t) {
        const int r = t >> 2, im = t & 3;
        cpa4(sb + 4u * (r * SLOT + im * IMS + sio),
             x + gio + r * (SIDE * BD) + im * DIM);
    }
    asm volatile("cp.async.commit_group;" ::: "memory");

    for (int c = 0; c < NCH; ++c) {
        const int p = c & 1;
        asm volatile("cp.async.wait_group 0;" ::: "memory");  // chunk c arrived
        __syncthreads();   // all async writes + silu(c-1) visible block-wide

        // (1) write back chunk c-1 from buf[p^1] (gather -> 32B-sector STG)
        if (c > 0) {
            const int gwb = gio + (c - 1) * (RCH * SIDE * BD);
#pragma unroll
            for (int t = 0; t < RCH * IPB; ++t) {
                const int r = t >> 2, im = t & 3;
                const float val = buf[((p ^ 1) * RCH + r) * SLOT + im * IMS + sio];
                out[gwb + r * (SIDE * BD) + im * DIM] = val;
            }
        }

        // (2) async-load chunk c+1 into buf[p^1] (same slots this thread just
        //     read in (1); same-thread program order makes the WAR safe)
        if (c + 1 < NCH) {
            const int gld = gio + (c + 1) * (RCH * SIDE * BD);
#pragma unroll
            for (int t = 0; t < RCH * IPB; ++t) {
                const int r = t >> 2, im = t & 3;
                cpa4(sb + 4u * (((p ^ 1) * RCH + r) * SLOT + im * IMS + sio),
                     x + gld + r * (SIDE * BD) + im * DIM);
            }
            asm volatile("cp.async.commit_group;" ::: "memory");
        }

        // (3) recurrence on chunk c (reads/writes buf[p] only)
#pragma unroll
        for (int r = 0; r < RCH; ++r) {
            const int base = (p * RCH + r) * SLOT + cbase + 4 * g;
            float xs[4];
#pragma unroll
            for (int cc = 0; cc < 4; ++cc) xs[cc] = buf[base + cc];

            float o0 = om * xs[0], o1 = om * xs[1];
            float o2 = om * xs[2], o3 = om * xs[3];

#pragma unroll
            for (int k = 0; k < 2; ++k) {
                // vertical update (elementwise per column)
                float v0 = fmaf(a2[k], h[k][0], fmaf(a1[k], v[k][0], b2[k] * xs[0]));
                float v1 = fmaf(a2[k], h[k][1], fmaf(a1[k], v[k][1], b2[k] * xs[1]));
                float v2 = fmaf(a2[k], h[k][2], fmaf(a1[k], v[k][2], b2[k] * xs[2]));
                float v3 = fmaf(a2[k], h[k][3], fmaf(a1[k], v[k][3], b2[k] * xs[3]));

                // v of the column left of this lane's chunk
                float vl = __shfl_up_sync(0xffffffffu, v3, 1);
                if (g == 0) vl = 0.f;

                // local serial prefix of h-drive
                float Y0 = fmaf(a2[k], vl, b1[k] * xs[0]);
                float Y1 = fmaf(a1[k], Y0, fmaf(a2[k], v0, b1[k] * xs[1]));
                float Y2 = fmaf(a1[k], Y1, fmaf(a2[k], v1, b1[k] * xs[2]));
                float Y3 = fmaf(a1[k], Y2, fmaf(a2[k], v2, b1[k] * xs[3]));

                // rematerialized coefficient powers
                const float p8  = p4[k] * p4[k];
                const float p16 = p8 * p8;
                const float p3  = p2[k] * a1[k];

                // 3-step scan over 8-lane group, coefficient a1^4
                float S = Y3, t;
                t = __shfl_up_sync(0xffffffffu, S, 1);
                if (g >= 1) S = fmaf(p4[k], t, S);
                t = __shfl_up_sync(0xffffffffu, S, 2);
                if (g >= 2) S = fmaf(p8, t, S);
                t = __shfl_up_sync(0xffffffffu, S, 4);
                if (g >= 4) S = fmaf(p16, t, S);

                // incoming h at the left chunk boundary
                float hin = __shfl_up_sync(0xffffffffu, S, 1);
                if (g == 0) hin = 0.f;

                // reconstruct h for the 4 owned columns
                float h0 = fmaf(a1[k], hin, Y0);
                float h1 = fmaf(p2[k], hin, Y1);
                float h2 = fmaf(p3,    hin, Y2);
                float h3 = fmaf(p4[k], hin, Y3);

                h[k][0] = h0; h[k][1] = h1; h[k][2] = h2; h[k][3] = h3;
                v[k][0] = v0; v[k][1] = v1; v[k][2] = v2; v[k][3] = v3;

                o0 = fmaf(c1[k], h0, fmaf(c2[k], v0, o0));
                o1 = fmaf(c1[k], h1, fmaf(c2[k], v1, o1));
                o2 = fmaf(c1[k], h2, fmaf(c2[k], v2, o2));
                o3 = fmaf(c1[k], h3, fmaf(c2[k], v3, o3));
            }

            // silu (tanh-based, 1 MUFU) + stage in place
            buf[base + 0] = silu_f(o0);
            buf[base + 1] = silu_f(o1);
            buf[base + 2] = silu_f(o2);
            buf[base + 3] = silu_f(o3);
        }
    }

    // ---- epilogue: write back final chunk ----
    __syncthreads();
    {
        const int q = (NCH - 1) & 1;
        const int gwb = gio + (NCH - 1) * (RCH * SIDE * BD);
#pragma unroll
        for (int t = 0; t < RCH * IPB; ++t) {
            const int r = t >> 2, im = t & 3;
            const float val = buf[(q * RCH + r) * SLOT + im * IMS + sio];
            out[gwb + r * (SIDE * BD) + im * DIM] = val;
        }
    }
}

extern "C" void kernel_launch(void* const* d_in, const int* in_sizes, int n_in,
                              void* d_out, int out_size)
{
    const float* x     = (const float*)d_in[0];
    const float* A1    = (const float*)d_in[1];
    const float* A2    = (const float*)d_in[2];
    const float* B1    = (const float*)d_in[3];
    const float* B2    = (const float*)d_in[4];
    const float* C1    = (const float*)d_in[5];
    const float* C2    = (const float*)d_in[6];
    const float* omega = (const float*)d_in[7];
    float* out = (float*)d_out;

    cudaFuncSetAttribute(ssm2d_kernel,
                         cudaFuncAttributeMaxDynamicSharedMemorySize, SMEM_BYTES);

    dim3 block(DPB * 32);                 // 256 threads
    dim3 grid(DIM / DPB, BSZ / IPB);      // 128 x 4 = 512 blocks
    ssm2d_kernel<<<grid, block, SMEM_BYTES>>>(x, A1, A2, B1, B2, C1, C2, omega, out);
}